// round 8
// baseline (speedup 1.0000x reference)
#include <cuda_runtime.h>
#include <cuda_bf16.h>
#include <math.h>

#define NB 2
#define SEQ 2048
#define DMODEL 1024
#define NHEAD 16
#define DHEAD 64
#define DFF 4096
#define NTOK (NB*SEQ)          // 4096

// ---------------- scratch (device globals; no runtime allocation) ----------------
__device__ float g_normed[(size_t)NTOK*DMODEL];
__device__ float g_q[(size_t)NTOK*DMODEL];
__device__ float g_k[(size_t)NTOK*DMODEL];
__device__ float g_v[(size_t)NTOK*DMODEL];
__device__ float g_scores[(size_t)NB*NHEAD*SEQ*SEQ];   // 512 MB
__device__ float g_ctx[(size_t)NTOK*DMODEL];
__device__ float g_hidden[(size_t)NTOK*DMODEL];
__device__ float g_ff1[(size_t)NTOK*DFF];
__device__ float g_ff2[(size_t)NTOK*DFF];
__device__ int   g_bucket[2*SEQ-1];

// ---------------- helpers ----------------
__device__ __forceinline__ unsigned f2tf32(float x)
{
    unsigned y;
    asm("cvt.rna.tf32.f32 %0, %1;" : "=r"(y) : "f"(x));
    return y;
}

// split x into tf32 hi + tf32 lo (3xTF32): hi+lo ~= x to ~2^-21
__device__ __forceinline__ uint2 split2(float x)
{
    unsigned h = f2tf32(x);
    float hf = __uint_as_float(h);
    unsigned l = f2tf32(x - hf);
    return make_uint2(h, l);
}

__device__ __forceinline__ void mma_tf32(float* d, const unsigned* a, const unsigned* b)
{
    asm volatile(
        "mma.sync.aligned.m16n8k8.row.col.f32.tf32.tf32.f32 "
        "{%0,%1,%2,%3}, {%4,%5,%6,%7}, {%8,%9}, {%0,%1,%2,%3};\n"
        : "+f"(d[0]), "+f"(d[1]), "+f"(d[2]), "+f"(d[3])
        : "r"(a[0]), "r"(a[1]), "r"(a[2]), "r"(a[3]),
          "r"(b[0]), "r"(b[1]));
}

// ---------------- RMSNorm: one block per row of 1024 ----------------
__global__ void rmsnorm_kernel(const float* __restrict__ x, const float* __restrict__ w,
                               float* __restrict__ out)
{
    int row = blockIdx.x;
    const float* xr = x + (long long)row * DMODEL;
    float* orow = out + (long long)row * DMODEL;
    int tid = threadIdx.x;

    float s = 0.f;
    for (int i = tid; i < DMODEL; i += 256) { float v = xr[i]; s += v * v; }

    __shared__ float red[256];
    red[tid] = s; __syncthreads();
    for (int st = 128; st > 0; st >>= 1) {
        if (tid < st) red[tid] += red[tid + st];
        __syncthreads();
    }
    float scale = rsqrtf(red[0] / (float)DMODEL + 1e-6f);

    for (int i = tid; i < DMODEL; i += 256)
        orow[i] = xr[i] * scale * w[i];
}

// ---------------- T5 relative-position bucket table ----------------
__global__ void bucket_kernel(int* __restrict__ table)
{
    int i = blockIdx.x * blockDim.x + threadIdx.x;
    if (i >= 2*SEQ - 1) return;
    int rel = i - (SEQ - 1);                // k - q
    int ret = (rel > 0) ? 16 : 0;
    int n = abs(rel);
    int bucket;
    if (n < 8) {
        bucket = n;
    } else {
        int vl = 8 + (int)(logf((float)n / 8.0f) / logf(16.0f) * 8.0f);
        bucket = min(vl, 15);
    }
    table[i] = ret + bucket;
}

// ---------------- fused bias + mask + softmax, single pass (regs) ----------------
__global__ void softmax_kernel(float* __restrict__ scores,
                               const float* __restrict__ rel_bias,   // [32,16]
                               const int* __restrict__ bucket,
                               const float* __restrict__ mask)       // [NB,SEQ]
{
    int qv = blockIdx.x, h = blockIdx.y, b = blockIdx.z;
    int tid = threadIdx.x;
    float* row = scores + (((long long)(b*NHEAD + h)) * SEQ + qv) * SEQ;

    __shared__ float red[256];

    float vals[8];
    float lmax = -1e30f;
    #pragma unroll
    for (int j = 0; j < 8; j++) {
        int k = tid + j * 256;
        float v = row[k]
                + rel_bias[bucket[k - qv + (SEQ-1)] * NHEAD + h]
                + (1.0f - mask[b*SEQ + k]) * -10000.0f;
        vals[j] = v;
        lmax = fmaxf(lmax, v);
    }
    red[tid] = lmax; __syncthreads();
    for (int st = 128; st > 0; st >>= 1) {
        if (tid < st) red[tid] = fmaxf(red[tid], red[tid + st]);
        __syncthreads();
    }
    float m = red[0];
    __syncthreads();

    float lsum = 0.f;
    #pragma unroll
    for (int j = 0; j < 8; j++) {
        float e = expf(vals[j] - m);
        vals[j] = e;
        lsum += e;
    }
    red[tid] = lsum; __syncthreads();
    for (int st = 128; st > 0; st >>= 1) {
        if (tid < st) red[tid] += red[tid + st];
        __syncthreads();
    }
    float inv = 1.0f / red[0];

    #pragma unroll
    for (int j = 0; j < 8; j++)
        row[tid + j * 256] = vals[j] * inv;
}

// ---------------- gelu_new(a) * g, in place into a ----------------
__global__ void gelumul_kernel(float* __restrict__ a, const float* __restrict__ g,
                               long long n)
{
    long long i = (long long)blockIdx.x * blockDim.x + threadIdx.x;
    if (i >= n) return;
    float x = a[i];
    float t = tanhf(0.7978845608028654f * (x + 0.044715f * x * x * x));
    a[i] = 0.5f * x * (1.0f + t) * g[i];
}

// ---------------- 3xTF32 tensor-core GEMM: C = A@B (+Res) ----------------
// 512 threads = 16 warps (4m x 4n). Block tile 128 x BN, warp tile 32 x (BN/4).
// Operands split to tf32 (hi,lo) at the smem STORE, stored interleaved so each
// fragment element is one conflict-free LDS.64.
//   A  layout: As[buf][m][k]{hi,lo}         word stride per m = 40
//   B  layout: Bs[buf][k][n]{hi,lo}         word stride per k = 2*(BN+4)
//   B^T layout: Bs[buf][n][k]{hi,lo}        word stride per n = 40
// acc += ahi*bhi + alo*bhi + ahi*blo (numerics identical to round-6 kernel).
template<int BN, bool TRANSB>
__global__ void __launch_bounds__(512, 1)
mma_gemm(const float* __restrict__ A, const float* __restrict__ B,
         const float* __restrict__ Res, float* __restrict__ C,
         int lda, int ldb, int ldc, int ldr, int K,
         int ZI,
         long long sAo, long long sAi, long long sBo, long long sBi,
         long long sCo, long long sCi)
{
    constexpr int BM = 128, BK = 16;
    constexpr int WN = BN / 4;                 // 32 or 16 cols per warp
    constexpr int NT = WN / 8;                 // 4 or 2 n-tiles per warp
    constexpr int ASTRW = 40;                  // words per A row (16 k * 2 + pad 8)
    constexpr int BSTRW = TRANSB ? 40 : 2 * (BN + 4);
    constexpr int AS_BUF = BM * ASTRW;         // 5120 words
    constexpr int BS_BUF = TRANSB ? BN * ASTRW : BK * BSTRW;

    extern __shared__ unsigned dsm[];
    unsigned* As = dsm;
    unsigned* Bs = dsm + 2 * AS_BUF;

    int z = blockIdx.z;
    int zo = z / ZI, zi = z - zo * ZI;
    A += zo * sAo + zi * sAi;
    B += zo * sBo + zi * sBi;
    C += zo * sCo + zi * sCi;

    int tid = threadIdx.x;
    int lane = tid & 31, wid = tid >> 5;
    int warp_m = wid >> 2, warp_n = wid & 3;
    int g = lane >> 2, t4 = lane & 3;
    int row0 = blockIdx.y * BM;
    int col0 = blockIdx.x * BN;

    float acc[2][NT][4];
    #pragma unroll
    for (int mi = 0; mi < 2; mi++)
        #pragma unroll
        for (int ni = 0; ni < NT; ni++)
            #pragma unroll
            for (int r = 0; r < 4; r++) acc[mi][ni][r] = 0.f;

    // gmem->smem coords (one vector load per thread per tile)
    int arow = tid >> 2, acol = (tid & 3) * 4;      // A: 128 x 16
    int brow, bcol;                                  // B
    if (TRANSB)      { brow = tid >> 2; bcol = (tid & 3) * 4; }   // 128 n x 16 k
    else if (BN==128){ brow = tid >> 5; bcol = (tid & 31) * 4; }  // 16 k x 128 n
    else             { brow = tid >> 5; bcol = (tid & 31) * 2; }  // 16 k x 64 n

    float4 aR; float4 bR4; float2 bR2;

    auto ldgA = [&](int k0) {
        aR = *reinterpret_cast<const float4*>(
            A + (long long)(row0 + arow) * lda + k0 + acol);
    };
    auto ldgB = [&](int k0) {
        if (TRANSB)
            bR4 = *reinterpret_cast<const float4*>(
                B + (long long)(col0 + brow) * ldb + k0 + bcol);
        else if (BN == 128)
            bR4 = *reinterpret_cast<const float4*>(
                B + (long long)(k0 + brow) * ldb + col0 + bcol);
        else
            bR2 = *reinterpret_cast<const float2*>(
                B + (long long)(k0 + brow) * ldb + col0 + bcol);
    };
    auto stsA = [&](int buf) {
        unsigned* base = &As[buf * AS_BUF + arow * ASTRW + acol * 2];
        float va[4] = {aR.x, aR.y, aR.z, aR.w};
        #pragma unroll
        for (int j = 0; j < 4; j++)
            *reinterpret_cast<uint2*>(base + j * 2) = split2(va[j]);
    };
    auto stsB = [&](int buf) {
        if (TRANSB) {
            unsigned* base = &Bs[buf * BS_BUF + brow * ASTRW + bcol * 2];
            float vb[4] = {bR4.x, bR4.y, bR4.z, bR4.w};
            #pragma unroll
            for (int j = 0; j < 4; j++)
                *reinterpret_cast<uint2*>(base + j * 2) = split2(vb[j]);
        } else if (BN == 128) {
            unsigned* base = &Bs[buf * BS_BUF + brow * BSTRW + bcol * 2];
            float vb[4] = {bR4.x, bR4.y, bR4.z, bR4.w};
            #pragma unroll
            for (int j = 0; j < 4; j++)
                *reinterpret_cast<uint2*>(base + j * 2) = split2(vb[j]);
        } else {
            unsigned* base = &Bs[buf * BS_BUF + brow * BSTRW + bcol * 2];
            *reinterpret_cast<uint2*>(base + 0) = split2(bR2.x);
            *reinterpret_cast<uint2*>(base + 2) = split2(bR2.y);
        }
    };

    ldgA(0); ldgB(0);
    stsA(0); stsB(0);
    __syncthreads();

    int cur = 0;
    for (int k0 = 0; k0 < K; k0 += BK) {
        bool more = (k0 + BK) < K;
        if (more) { ldgA(k0 + BK); ldgB(k0 + BK); }

        #pragma unroll
        for (int kk = 0; kk < BK; kk += 8) {
            // A fragments: one LDS.64 each, conflict-free
            uint2 afr[2][4];
            #pragma unroll
            for (int mi = 0; mi < 2; mi++) {
                int m = warp_m * 32 + mi * 16 + g;
                const unsigned* base = &As[cur * AS_BUF + m * ASTRW + (kk + t4) * 2];
                afr[mi][0] = *reinterpret_cast<const uint2*>(base);
                afr[mi][1] = *reinterpret_cast<const uint2*>(base + 8 * ASTRW);
                afr[mi][2] = *reinterpret_cast<const uint2*>(base + 8);
                afr[mi][3] = *reinterpret_cast<const uint2*>(base + 8 * ASTRW + 8);
            }
            uint2 bfr[NT][2];
            #pragma unroll
            for (int ni = 0; ni < NT; ni++) {
                int n = warp_n * WN + ni * 8 + g;
                if (TRANSB) {
                    const unsigned* base = &Bs[cur * BS_BUF + n * ASTRW + (kk + t4) * 2];
                    bfr[ni][0] = *reinterpret_cast<const uint2*>(base);
                    bfr[ni][1] = *reinterpret_cast<const uint2*>(base + 8);
                } else {
                    const unsigned* base = &Bs[cur * BS_BUF + (kk + t4) * BSTRW + n * 2];
                    bfr[ni][0] = *reinterpret_cast<const uint2*>(base);
                    bfr[ni][1] = *reinterpret_cast<const uint2*>(base + 4 * BSTRW);
                }
            }
            #pragma unroll
            for (int mi = 0; mi < 2; mi++) {
                unsigned AH[4] = {afr[mi][0].x, afr[mi][1].x, afr[mi][2].x, afr[mi][3].x};
                unsigned AL[4] = {afr[mi][0].y, afr[mi][1].y, afr[mi][2].y, afr[mi][3].y};
                #pragma unroll
                for (int ni = 0; ni < NT; ni++) {
                    unsigned BH[2] = {bfr[ni][0].x, bfr[ni][1].x};
                    unsigned BL[2] = {bfr[ni][0].y, bfr[ni][1].y};
                    mma_tf32(acc[mi][ni], AH, BH);
                    mma_tf32(acc[mi][ni], AL, BH);
                    mma_tf32(acc[mi][ni], AH, BL);
                }
            }
        }

        if (more) { stsA(cur ^ 1); stsB(cur ^ 1); }
        __syncthreads();
        cur ^= 1;
    }

    // epilogue: d0,d1 at (r, c..c+1); d2,d3 at (r+8, c..c+1)
    #pragma unroll
    for (int mi = 0; mi < 2; mi++) {
        #pragma unroll
        for (int ni = 0; ni < NT; ni++) {
            int r = row0 + warp_m * 32 + mi * 16 + g;
            int c = col0 + warp_n * WN + ni * 8 + t4 * 2;
            float2 v0 = make_float2(acc[mi][ni][0], acc[mi][ni][1]);
            float2 v1 = make_float2(acc[mi][ni][2], acc[mi][ni][3]);
            if (Res) {
                float2 r0 = *reinterpret_cast<const float2*>(Res + (long long)r * ldr + c);
                float2 r1 = *reinterpret_cast<const float2*>(Res + (long long)(r + 8) * ldr + c);
                v0.x += r0.x; v0.y += r0.y;
                v1.x += r1.x; v1.y += r1.y;
            }
            *reinterpret_cast<float2*>(C + (long long)r * ldc + c) = v0;
            *reinterpret_cast<float2*>(C + (long long)(r + 8) * ldc + c) = v1;
        }
    }
}

// dynamic smem sizes (bytes)
#define SMEM_GEMM_128F ((2*128*40 + 2*16*264) * 4)   // 74752
#define SMEM_GEMM_128T ((2*128*40 + 2*128*40) * 4)   // 81920
#define SMEM_GEMM_64F  ((2*128*40 + 2*16*136) * 4)   // 58368

// ---------------- host orchestration ----------------
extern "C" void kernel_launch(void* const* d_in, const int* in_sizes, int n_in,
                              void* d_out, int out_size)
{
    const float* hidden   = (const float*)d_in[0];
    const float* mask     = (const float*)d_in[1];
    const float* ln1_w    = (const float*)d_in[2];
    const float* wq       = (const float*)d_in[3];
    const float* wk       = (const float*)d_in[4];
    const float* wv       = (const float*)d_in[5];
    const float* rel_bias = (const float*)d_in[6];
    const float* wo       = (const float*)d_in[7];
    const float* ln2_w    = (const float*)d_in[8];
    const float* w1       = (const float*)d_in[9];
    const float* w2       = (const float*)d_in[10];
    const float* w_out    = (const float*)d_in[11];
    float* out = (float*)d_out;

    cudaFuncSetAttribute(reinterpret_cast<const void*>(&mma_gemm<128,false>),
                         cudaFuncAttributeMaxDynamicSharedMemorySize, SMEM_GEMM_128F);
    cudaFuncSetAttribute(reinterpret_cast<const void*>(&mma_gemm<128,true>),
                         cudaFuncAttributeMaxDynamicSharedMemorySize, SMEM_GEMM_128T);
    cudaFuncSetAttribute(reinterpret_cast<const void*>(&mma_gemm<64,false>),
                         cudaFuncAttributeMaxDynamicSharedMemorySize, SMEM_GEMM_64F);

    void* p;
    cudaGetSymbolAddress(&p, g_normed); float* normed = (float*)p;
    cudaGetSymbolAddress(&p, g_q);      float* q      = (float*)p;
    cudaGetSymbolAddress(&p, g_k);      float* k      = (float*)p;
    cudaGetSymbolAddress(&p, g_v);      float* v      = (float*)p;
    cudaGetSymbolAddress(&p, g_scores); float* scores = (float*)p;
    cudaGetSymbolAddress(&p, g_ctx);    float* ctx    = (float*)p;
    cudaGetSymbolAddress(&p, g_hidden); float* hid    = (float*)p;
    cudaGetSymbolAddress(&p, g_ff1);    float* ff1    = (float*)p;
    cudaGetSymbolAddress(&p, g_ff2);    float* ff2    = (float*)p;
    cudaGetSymbolAddress(&p, g_bucket); int*   bucket = (int*)p;

    const long long SD  = (long long)SEQ * DMODEL;   // per-batch token-plane stride
    const long long SS2 = (long long)SEQ * SEQ;      // per-head score plane

    // 1. RMSNorm #1
    rmsnorm_kernel<<<NTOK, 256>>>(hidden, ln1_w, normed);

    // 2. QKV projections: [4096,1024] x [1024,1024]
    dim3 gProj(DMODEL / 128, NTOK / 128, 1);
    mma_gemm<128,false><<<gProj, 512, SMEM_GEMM_128F>>>(normed, wq, nullptr, q,
        DMODEL, DMODEL, DMODEL, 0, DMODEL,
        1, 0,0, 0,0, 0,0);
    mma_gemm<128,false><<<gProj, 512, SMEM_GEMM_128F>>>(normed, wk, nullptr, k,
        DMODEL, DMODEL, DMODEL, 0, DMODEL,
        1, 0,0, 0,0, 0,0);
    mma_gemm<128,false><<<gProj, 512, SMEM_GEMM_128F>>>(normed, wv, nullptr, v,
        DMODEL, DMODEL, DMODEL, 0, DMODEL,
        1, 0,0, 0,0, 0,0);

    // 3. bucket table
    bucket_kernel<<<(2*SEQ - 1 + 255) / 256, 256>>>(bucket);

    // 4. scores = Q @ K^T per (b,h): M=N=2048, K=64
    dim3 gScore(SEQ / 128, SEQ / 128, NB * NHEAD);
    mma_gemm<128,true><<<gScore, 512, SMEM_GEMM_128T>>>(q, k, nullptr, scores,
        DMODEL, DMODEL, SEQ, 0, DHEAD,
        NHEAD, SD, DHEAD, SD, DHEAD, (long long)NHEAD * SS2, SS2);

    // 5. bias + mask + softmax (single pass, in place)
    dim3 gSm(SEQ, NHEAD, NB);
    softmax_kernel<<<gSm, 256>>>(scores, rel_bias, bucket, mask);

    // 6. ctx = probs @ V per (b,h): M=2048, N=64, K=2048
    dim3 gPV(1, SEQ / 128, NB * NHEAD);
    mma_gemm<64,false><<<gPV, 512, SMEM_GEMM_64F>>>(scores, v, nullptr, ctx,
        SEQ, DMODEL, DMODEL, 0, SEQ,
        NHEAD, (long long)NHEAD * SS2, SS2, SD, DHEAD, SD, DHEAD);

    // 7. hidden = hidden_in + ctx @ wo
    mma_gemm<128,false><<<gProj, 512, SMEM_GEMM_128F>>>(ctx, wo, hidden, hid,
        DMODEL, DMODEL, DMODEL, DMODEL, DMODEL,
        1, 0,0, 0,0, 0,0);

    // 8. RMSNorm #2 (reuse normed buffer)
    rmsnorm_kernel<<<NTOK, 256>>>(hid, ln2_w, normed);

    // 9. ff1 = normed2 @ w1 ; ff2 = normed2 @ w2   [4096,1024]x[1024,4096]
    dim3 gFF(DFF / 128, NTOK / 128, 1);
    mma_gemm<128,false><<<gFF, 512, SMEM_GEMM_128F>>>(normed, w1, nullptr, ff1,
        DMODEL, DFF, DFF, 0, DMODEL,
        1, 0,0, 0,0, 0,0);
    mma_gemm<128,false><<<gFF, 512, SMEM_GEMM_128F>>>(normed, w2, nullptr, ff2,
        DMODEL, DFF, DFF, 0, DMODEL,
        1, 0,0, 0,0, 0,0);

    // 10. ff1 = gelu_new(ff1) * ff2
    long long nff = (long long)NTOK * DFF;
    gelumul_kernel<<<(unsigned)((nff + 255) / 256), 256>>>(ff1, ff2, nff);

    // 11. out = hidden + ff1 @ w_out   [4096,4096]x[4096,1024]
    mma_gemm<128,false><<<gProj, 512, SMEM_GEMM_128F>>>(ff1, w_out, hid, out,
        DFF, DMODEL, DMODEL, DMODEL, DFF,
        1, 0,0, 0,0, 0,0);
}

// round 9
// speedup vs baseline: 1.7980x; 1.7980x over previous
#include <cuda_runtime.h>
#include <cuda_bf16.h>
#include <math.h>

#define NB 2
#define SEQ 2048
#define DMODEL 1024
#define NHEAD 16
#define DHEAD 64
#define DFF 4096
#define NTOK (NB*SEQ)          // 4096

// ---------------- scratch (device globals; no runtime allocation) ----------------
__device__ float g_normed[(size_t)NTOK*DMODEL];
__device__ float g_q[(size_t)NTOK*DMODEL];
__device__ float g_k[(size_t)NTOK*DMODEL];
__device__ float g_v[(size_t)NTOK*DMODEL];
__device__ float g_scores[(size_t)NB*NHEAD*SEQ*SEQ];   // 512 MB
__device__ float g_ctx[(size_t)NTOK*DMODEL];
__device__ float g_hidden[(size_t)NTOK*DMODEL];
__device__ float g_ff1[(size_t)NTOK*DFF];
__device__ float g_ff2[(size_t)NTOK*DFF];
__device__ int   g_bucket[2*SEQ-1];

// ---------------- helpers ----------------
__device__ __forceinline__ unsigned f2tf32(float x)
{
    unsigned y;
    asm("cvt.rna.tf32.f32 %0, %1;" : "=r"(y) : "f"(x));
    return y;
}

// split x into tf32 hi + tf32 lo (3xTF32): hi+lo ~= x to ~2^-21
__device__ __forceinline__ void split_tf32(float x, unsigned& hi, unsigned& lo)
{
    unsigned h = f2tf32(x);
    float hf = __uint_as_float(h);
    hi = h;
    lo = f2tf32(x - hf);
}

__device__ __forceinline__ void mma_tf32(float* d, const unsigned* a, const unsigned* b)
{
    asm volatile(
        "mma.sync.aligned.m16n8k8.row.col.f32.tf32.tf32.f32 "
        "{%0,%1,%2,%3}, {%4,%5,%6,%7}, {%8,%9}, {%0,%1,%2,%3};\n"
        : "+f"(d[0]), "+f"(d[1]), "+f"(d[2]), "+f"(d[3])
        : "r"(a[0]), "r"(a[1]), "r"(a[2]), "r"(a[3]),
          "r"(b[0]), "r"(b[1]));
}

__device__ __forceinline__ void cp16(float* smem_dst, const float* gmem_src)
{
    unsigned s = (unsigned)__cvta_generic_to_shared(smem_dst);
    asm volatile("cp.async.cg.shared.global [%0], [%1], 16;\n"
                 :: "r"(s), "l"(gmem_src));
}
__device__ __forceinline__ void cp_commit()
{
    asm volatile("cp.async.commit_group;\n" ::: "memory");
}
__device__ __forceinline__ void cp_wait_all()
{
    asm volatile("cp.async.wait_group 0;\n" ::: "memory");
}

// ---------------- RMSNorm: one block per row of 1024 ----------------
__global__ void rmsnorm_kernel(const float* __restrict__ x, const float* __restrict__ w,
                               float* __restrict__ out)
{
    int row = blockIdx.x;
    const float* xr = x + (long long)row * DMODEL;
    float* orow = out + (long long)row * DMODEL;
    int tid = threadIdx.x;

    float s = 0.f;
    for (int i = tid; i < DMODEL; i += 256) { float v = xr[i]; s += v * v; }

    __shared__ float red[256];
    red[tid] = s; __syncthreads();
    for (int st = 128; st > 0; st >>= 1) {
        if (tid < st) red[tid] += red[tid + st];
        __syncthreads();
    }
    float scale = rsqrtf(red[0] / (float)DMODEL + 1e-6f);

    for (int i = tid; i < DMODEL; i += 256)
        orow[i] = xr[i] * scale * w[i];
}

// ---------------- T5 relative-position bucket table ----------------
__global__ void bucket_kernel(int* __restrict__ table)
{
    int i = blockIdx.x * blockDim.x + threadIdx.x;
    if (i >= 2*SEQ - 1) return;
    int rel = i - (SEQ - 1);                // k - q
    int ret = (rel > 0) ? 16 : 0;
    int n = abs(rel);
    int bucket;
    if (n < 8) {
        bucket = n;
    } else {
        int vl = 8 + (int)(logf((float)n / 8.0f) / logf(16.0f) * 8.0f);
        bucket = min(vl, 15);
    }
    table[i] = ret + bucket;
}

// ---------------- fused bias + mask + softmax, single pass (regs) ----------------
__global__ void softmax_kernel(float* __restrict__ scores,
                               const float* __restrict__ rel_bias,   // [32,16]
                               const int* __restrict__ bucket,
                               const float* __restrict__ mask)       // [NB,SEQ]
{
    int qv = blockIdx.x, h = blockIdx.y, b = blockIdx.z;
    int tid = threadIdx.x;
    float* row = scores + (((long long)(b*NHEAD + h)) * SEQ + qv) * SEQ;

    __shared__ float red[256];

    float vals[8];
    float lmax = -1e30f;
    #pragma unroll
    for (int j = 0; j < 8; j++) {
        int k = tid + j * 256;
        float v = row[k]
                + rel_bias[bucket[k - qv + (SEQ-1)] * NHEAD + h]
                + (1.0f - mask[b*SEQ + k]) * -10000.0f;
        vals[j] = v;
        lmax = fmaxf(lmax, v);
    }
    red[tid] = lmax; __syncthreads();
    for (int st = 128; st > 0; st >>= 1) {
        if (tid < st) red[tid] = fmaxf(red[tid], red[tid + st]);
        __syncthreads();
    }
    float m = red[0];
    __syncthreads();

    float lsum = 0.f;
    #pragma unroll
    for (int j = 0; j < 8; j++) {
        float e = expf(vals[j] - m);
        vals[j] = e;
        lsum += e;
    }
    red[tid] = lsum; __syncthreads();
    for (int st = 128; st > 0; st >>= 1) {
        if (tid < st) red[tid] += red[tid + st];
        __syncthreads();
    }
    float inv = 1.0f / red[0];

    #pragma unroll
    for (int j = 0; j < 8; j++)
        row[tid + j * 256] = vals[j] * inv;
}

// ---------------- gelu_new(a) * g, in place into a ----------------
__global__ void gelumul_kernel(float* __restrict__ a, const float* __restrict__ g,
                               long long n)
{
    long long i = (long long)blockIdx.x * blockDim.x + threadIdx.x;
    if (i >= n) return;
    float x = a[i];
    float t = tanhf(0.7978845608028654f * (x + 0.044715f * x * x * x));
    a[i] = 0.5f * x * (1.0f + t) * g[i];
}

// ---------------- 3xTF32 tensor-core GEMM: C = A@B (+Res) ----------------
// BM=128, BK=16, BN templated (128 or 64). 256 threads = 8 warps (4m x 2n).
// Warp tile: 32 x (BN/2) = 2 x NT m16n8k8 fragments.
// fp32 operands in smem (cp.async double-buffered); tf32 (hi,lo) split at
// fragment load; acc += ahi*bhi + alo*bhi + ahi*blo.
// ASTR=20 -> A frag banks 20g+t4: all 32 distinct (conflict-free).
// BSTR=BN+8 -> B frag banks 8*t4+g: all 32 distinct (conflict-free).
// TRANSB: B element (k,n) = B[n*ldb + k] (register-staged transpose store).
template<int BN, bool TRANSB>
__global__ void __launch_bounds__(256, 2)
mma_gemm(const float* __restrict__ A, const float* __restrict__ B,
         const float* __restrict__ Res, float* __restrict__ C,
         int lda, int ldb, int ldc, int ldr, int K,
         int ZI,
         long long sAo, long long sAi, long long sBo, long long sBi,
         long long sCo, long long sCi)
{
    constexpr int BM = 128, BK = 16;
    constexpr int ASTR = 20;              // BK + 4
    constexpr int BSTR = BN + 8;          // 136 / 72
    constexpr int WN = BN / 2;            // 64 / 32 cols per warp
    constexpr int NT = WN / 8;            // 8 / 4 n-tiles per warp
    constexpr int NBLK = NT / 4;          // 2 / 1 register-blocked groups
    constexpr int BLD = TRANSB ? 2 : (BN / 64);   // vector loads per thread for B

    __shared__ __align__(16) float As[2][BM * ASTR];
    __shared__ __align__(16) float Bs[2][BK * BSTR];

    int z = blockIdx.z;
    int zo = z / ZI, zi = z - zo * ZI;
    A += zo * sAo + zi * sAi;
    B += zo * sBo + zi * sBi;
    C += zo * sCo + zi * sCi;

    int tid = threadIdx.x;
    int lane = tid & 31, wid = tid >> 5;
    int warp_m = wid >> 1, warp_n = wid & 1;
    int g = lane >> 2, t4 = lane & 3;
    int row0 = blockIdx.y * BM;
    int col0 = blockIdx.x * BN;

    float acc[2][NT][4];
    #pragma unroll
    for (int mi = 0; mi < 2; mi++)
        #pragma unroll
        for (int ni = 0; ni < NT; ni++)
            #pragma unroll
            for (int r = 0; r < 4; r++) acc[mi][ni][r] = 0.f;

    // A tile: 128 x 16, two 16B transfers per thread
    int arow[2], acol[2];
    #pragma unroll
    for (int it = 0; it < 2; it++) {
        int i = tid + it * 256;
        arow[it] = i >> 2;
        acol[it] = (i & 3) * 4;
    }

    auto issueA = [&](int buf, int k0) {
        #pragma unroll
        for (int it = 0; it < 2; it++)
            cp16(&As[buf][arow[it] * ASTR + acol[it]],
                 A + (long long)(row0 + arow[it]) * lda + k0 + acol[it]);
    };
    auto issueB = [&](int buf, int k0) {   // !TRANSB only
        #pragma unroll
        for (int it = 0; it < BLD; it++) {
            int i = tid + it * 256;
            int kr = (BN == 128) ? (i >> 5) : (i >> 4);
            int nq = (BN == 128) ? ((i & 31) * 4) : ((i & 15) * 4);
            cp16(&Bs[buf][kr * BSTR + nq],
                 B + (long long)(k0 + kr) * ldb + col0 + nq);
        }
    };

    float4 bR[BLD];
    auto ldgBT = [&](int k0) {             // TRANSB staging
        #pragma unroll
        for (int it = 0; it < BLD; it++) {
            int i = tid + it * 256;
            int n = i >> 2, kq = (i & 3) * 4;
            bR[it] = *reinterpret_cast<const float4*>(
                B + (long long)(col0 + n) * ldb + k0 + kq);
        }
    };
    auto stsBT = [&](int buf) {
        #pragma unroll
        for (int it = 0; it < BLD; it++) {
            int i = tid + it * 256;
            int n = i >> 2, kq = (i & 3) * 4;
            Bs[buf][(kq + 0) * BSTR + n] = bR[it].x;
            Bs[buf][(kq + 1) * BSTR + n] = bR[it].y;
            Bs[buf][(kq + 2) * BSTR + n] = bR[it].z;
            Bs[buf][(kq + 3) * BSTR + n] = bR[it].w;
        }
    };

    // prologue: fill buffer 0
    issueA(0, 0);
    if (!TRANSB) issueB(0, 0);
    cp_commit();
    if (TRANSB) { ldgBT(0); stsBT(0); }
    cp_wait_all();
    __syncthreads();

    int cur = 0;
    for (int k0 = 0; k0 < K; k0 += BK) {
        bool more = (k0 + BK) < K;
        if (more) {
            issueA(cur ^ 1, k0 + BK);
            if (!TRANSB) issueB(cur ^ 1, k0 + BK);
            cp_commit();
            if (TRANSB) ldgBT(k0 + BK);
        }

        #pragma unroll
        for (int kk = 0; kk < BK; kk += 8) {
            // A fragments: conflict-free LDS.32, split once per kk
            unsigned afh[2][4], afl[2][4];
            #pragma unroll
            for (int mi = 0; mi < 2; mi++) {
                int m = warp_m * 32 + mi * 16 + g;
                float a0 = As[cur][ m      * ASTR + kk + t4];
                float a1 = As[cur][(m + 8) * ASTR + kk + t4];
                float a2 = As[cur][ m      * ASTR + kk + t4 + 4];
                float a3 = As[cur][(m + 8) * ASTR + kk + t4 + 4];
                split_tf32(a0, afh[mi][0], afl[mi][0]);
                split_tf32(a1, afh[mi][1], afl[mi][1]);
                split_tf32(a2, afh[mi][2], afl[mi][2]);
                split_tf32(a3, afh[mi][3], afl[mi][3]);
            }
            // B fragments in register-blocked groups of 4 ni (caps reg pressure)
            #pragma unroll
            for (int nb = 0; nb < NBLK; nb++) {
                unsigned bfh[4][2], bfl[4][2];
                #pragma unroll
                for (int nj = 0; nj < 4; nj++) {
                    int n = warp_n * WN + (nb * 4 + nj) * 8 + g;
                    float b0 = Bs[cur][(kk + t4    ) * BSTR + n];
                    float b1 = Bs[cur][(kk + t4 + 4) * BSTR + n];
                    split_tf32(b0, bfh[nj][0], bfl[nj][0]);
                    split_tf32(b1, bfh[nj][1], bfl[nj][1]);
                }
                #pragma unroll
                for (int mi = 0; mi < 2; mi++)
                    #pragma unroll
                    for (int nj = 0; nj < 4; nj++) {
                        float* d = acc[mi][nb * 4 + nj];
                        mma_tf32(d, afh[mi], bfh[nj]);
                        mma_tf32(d, afl[mi], bfh[nj]);
                        mma_tf32(d, afh[mi], bfl[nj]);
                    }
            }
        }

        if (more) {
            if (TRANSB) stsBT(cur ^ 1);
            cp_wait_all();
        }
        __syncthreads();
        cur ^= 1;
    }

    // epilogue: d0,d1 at (r, c..c+1); d2,d3 at (r+8, c..c+1)
    #pragma unroll
    for (int mi = 0; mi < 2; mi++) {
        #pragma unroll
        for (int ni = 0; ni < NT; ni++) {
            int r = row0 + warp_m * 32 + mi * 16 + g;
            int c = col0 + warp_n * WN + ni * 8 + t4 * 2;
            float2 v0 = make_float2(acc[mi][ni][0], acc[mi][ni][1]);
            float2 v1 = make_float2(acc[mi][ni][2], acc[mi][ni][3]);
            if (Res) {
                float2 r0 = *reinterpret_cast<const float2*>(Res + (long long)r * ldr + c);
                float2 r1 = *reinterpret_cast<const float2*>(Res + (long long)(r + 8) * ldr + c);
                v0.x += r0.x; v0.y += r0.y;
                v1.x += r1.x; v1.y += r1.y;
            }
            *reinterpret_cast<float2*>(C + (long long)r * ldc + c) = v0;
            *reinterpret_cast<float2*>(C + (long long)(r + 8) * ldc + c) = v1;
        }
    }
}

// ---------------- host orchestration ----------------
extern "C" void kernel_launch(void* const* d_in, const int* in_sizes, int n_in,
                              void* d_out, int out_size)
{
    const float* hidden   = (const float*)d_in[0];
    const float* mask     = (const float*)d_in[1];
    const float* ln1_w    = (const float*)d_in[2];
    const float* wq       = (const float*)d_in[3];
    const float* wk       = (const float*)d_in[4];
    const float* wv       = (const float*)d_in[5];
    const float* rel_bias = (const float*)d_in[6];
    const float* wo       = (const float*)d_in[7];
    const float* ln2_w    = (const float*)d_in[8];
    const float* w1       = (const float*)d_in[9];
    const float* w2       = (const float*)d_in[10];
    const float* w_out    = (const float*)d_in[11];
    float* out = (float*)d_out;

    void* p;
    cudaGetSymbolAddress(&p, g_normed); float* normed = (float*)p;
    cudaGetSymbolAddress(&p, g_q);      float* q      = (float*)p;
    cudaGetSymbolAddress(&p, g_k);      float* k      = (float*)p;
    cudaGetSymbolAddress(&p, g_v);      float* v      = (float*)p;
    cudaGetSymbolAddress(&p, g_scores); float* scores = (float*)p;
    cudaGetSymbolAddress(&p, g_ctx);    float* ctx    = (float*)p;
    cudaGetSymbolAddress(&p, g_hidden); float* hid    = (float*)p;
    cudaGetSymbolAddress(&p, g_ff1);    float* ff1    = (float*)p;
    cudaGetSymbolAddress(&p, g_ff2);    float* ff2    = (float*)p;
    cudaGetSymbolAddress(&p, g_bucket); int*   bucket = (int*)p;

    const long long SD  = (long long)SEQ * DMODEL;   // per-batch token-plane stride
    const long long SS2 = (long long)SEQ * SEQ;      // per-head score plane

    // 1. RMSNorm #1
    rmsnorm_kernel<<<NTOK, 256>>>(hidden, ln1_w, normed);

    // 2. QKV projections: [4096,1024] x [1024,1024]
    dim3 gProj(DMODEL / 128, NTOK / 128, 1);
    mma_gemm<128,false><<<gProj, 256>>>(normed, wq, nullptr, q,
        DMODEL, DMODEL, DMODEL, 0, DMODEL,
        1, 0,0, 0,0, 0,0);
    mma_gemm<128,false><<<gProj, 256>>>(normed, wk, nullptr, k,
        DMODEL, DMODEL, DMODEL, 0, DMODEL,
        1, 0,0, 0,0, 0,0);
    mma_gemm<128,false><<<gProj, 256>>>(normed, wv, nullptr, v,
        DMODEL, DMODEL, DMODEL, 0, DMODEL,
        1, 0,0, 0,0, 0,0);

    // 3. bucket table
    bucket_kernel<<<(2*SEQ - 1 + 255) / 256, 256>>>(bucket);

    // 4. scores = Q @ K^T per (b,h): M=N=2048, K=64
    dim3 gScore(SEQ / 128, SEQ / 128, NB * NHEAD);
    mma_gemm<128,true><<<gScore, 256>>>(q, k, nullptr, scores,
        DMODEL, DMODEL, SEQ, 0, DHEAD,
        NHEAD, SD, DHEAD, SD, DHEAD, (long long)NHEAD * SS2, SS2);

    // 5. bias + mask + softmax (single pass, in place)
    dim3 gSm(SEQ, NHEAD, NB);
    softmax_kernel<<<gSm, 256>>>(scores, rel_bias, bucket, mask);

    // 6. ctx = probs @ V per (b,h): M=2048, N=64, K=2048
    dim3 gPV(1, SEQ / 128, NB * NHEAD);
    mma_gemm<64,false><<<gPV, 256>>>(scores, v, nullptr, ctx,
        SEQ, DMODEL, DMODEL, 0, SEQ,
        NHEAD, (long long)NHEAD * SS2, SS2, SD, DHEAD, SD, DHEAD);

    // 7. hidden = hidden_in + ctx @ wo
    mma_gemm<128,false><<<gProj, 256>>>(ctx, wo, hidden, hid,
        DMODEL, DMODEL, DMODEL, DMODEL, DMODEL,
        1, 0,0, 0,0, 0,0);

    // 8. RMSNorm #2 (reuse normed buffer)
    rmsnorm_kernel<<<NTOK, 256>>>(hid, ln2_w, normed);

    // 9. ff1 = normed2 @ w1 ; ff2 = normed2 @ w2   [4096,1024]x[1024,4096]
    dim3 gFF(DFF / 128, NTOK / 128, 1);
    mma_gemm<128,false><<<gFF, 256>>>(normed, w1, nullptr, ff1,
        DMODEL, DFF, DFF, 0, DMODEL,
        1, 0,0, 0,0, 0,0);
    mma_gemm<128,false><<<gFF, 256>>>(normed, w2, nullptr, ff2,
        DMODEL, DFF, DFF, 0, DMODEL,
        1, 0,0, 0,0, 0,0);

    // 10. ff1 = gelu_new(ff1) * ff2
    long long nff = (long long)NTOK * DFF;
    gelumul_kernel<<<(unsigned)((nff + 255) / 256), 256>>>(ff1, ff2, nff);

    // 11. out = hidden + ff1 @ w_out   [4096,4096]x[4096,1024]
    mma_gemm<128,false><<<gProj, 256>>>(ff1, w_out, hid, out,
        DFF, DMODEL, DMODEL, DMODEL, DFF,
        1, 0,0, 0,0, 0,0);
}

// round 10
// speedup vs baseline: 2.3743x; 1.3206x over previous
#include <cuda_runtime.h>
#include <cuda_bf16.h>
#include <math.h>

#define NB 2
#define SEQ 2048
#define DMODEL 1024
#define NHEAD 16
#define DHEAD 64
#define DFF 4096
#define NTOK (NB*SEQ)          // 4096

// ---------------- scratch (device globals; no runtime allocation) ----------------
__device__ float g_normed[(size_t)NTOK*DMODEL];
__device__ float g_q[(size_t)NTOK*DMODEL];
__device__ float g_k[(size_t)NTOK*DMODEL];
__device__ float g_v[(size_t)NTOK*DMODEL];
__device__ float g_scores[(size_t)NB*NHEAD*SEQ*SEQ];   // 512 MB
__device__ float g_ctx[(size_t)NTOK*DMODEL];
__device__ float g_hidden[(size_t)NTOK*DMODEL];
__device__ float g_ff1[(size_t)NTOK*DFF];
__device__ float g_ff2[(size_t)NTOK*DFF];
__device__ int   g_bucket[2*SEQ-1];

// ---------------- helpers ----------------
// Split two consecutive-k fp32 values into packed bf16x2 (hi, lo) planes.
// hi = bf16(x); lo = bf16(x - hi).  Even k in low 16 bits.
__device__ __forceinline__ uint2 split_pack(float e, float o)
{
    __nv_bfloat16 he = __float2bfloat16(e);
    __nv_bfloat16 ho = __float2bfloat16(o);
    __nv_bfloat16 le = __float2bfloat16(e - __bfloat162float(he));
    __nv_bfloat16 lo = __float2bfloat16(o - __bfloat162float(ho));
    unsigned uh = (unsigned)__bfloat16_as_ushort(he) |
                  ((unsigned)__bfloat16_as_ushort(ho) << 16);
    unsigned ul = (unsigned)__bfloat16_as_ushort(le) |
                  ((unsigned)__bfloat16_as_ushort(lo) << 16);
    return make_uint2(uh, ul);
}

__device__ __forceinline__ void mma_bf16(float* d, const unsigned* a, const unsigned* b)
{
    asm volatile(
        "mma.sync.aligned.m16n8k16.row.col.f32.bf16.bf16.f32 "
        "{%0,%1,%2,%3}, {%4,%5,%6,%7}, {%8,%9}, {%0,%1,%2,%3};\n"
        : "+f"(d[0]), "+f"(d[1]), "+f"(d[2]), "+f"(d[3])
        : "r"(a[0]), "r"(a[1]), "r"(a[2]), "r"(a[3]),
          "r"(b[0]), "r"(b[1]));
}

// ---------------- RMSNorm: one block per row of 1024 ----------------
__global__ void rmsnorm_kernel(const float* __restrict__ x, const float* __restrict__ w,
                               float* __restrict__ out)
{
    int row = blockIdx.x;
    const float* xr = x + (long long)row * DMODEL;
    float* orow = out + (long long)row * DMODEL;
    int tid = threadIdx.x;

    float s = 0.f;
    for (int i = tid; i < DMODEL; i += 256) { float v = xr[i]; s += v * v; }

    __shared__ float red[256];
    red[tid] = s; __syncthreads();
    for (int st = 128; st > 0; st >>= 1) {
        if (tid < st) red[tid] += red[tid + st];
        __syncthreads();
    }
    float scale = rsqrtf(red[0] / (float)DMODEL + 1e-6f);

    for (int i = tid; i < DMODEL; i += 256)
        orow[i] = xr[i] * scale * w[i];
}

// ---------------- T5 relative-position bucket table ----------------
__global__ void bucket_kernel(int* __restrict__ table)
{
    int i = blockIdx.x * blockDim.x + threadIdx.x;
    if (i >= 2*SEQ - 1) return;
    int rel = i - (SEQ - 1);                // k - q
    int ret = (rel > 0) ? 16 : 0;
    int n = abs(rel);
    int bucket;
    if (n < 8) {
        bucket = n;
    } else {
        int vl = 8 + (int)(logf((float)n / 8.0f) / logf(16.0f) * 8.0f);
        bucket = min(vl, 15);
    }
    table[i] = ret + bucket;
}

// ---------------- fused bias + mask + softmax, single pass (regs) ----------------
__global__ void softmax_kernel(float* __restrict__ scores,
                               const float* __restrict__ rel_bias,   // [32,16]
                               const int* __restrict__ bucket,
                               const float* __restrict__ mask)       // [NB,SEQ]
{
    int qv = blockIdx.x, h = blockIdx.y, b = blockIdx.z;
    int tid = threadIdx.x;
    float* row = scores + (((long long)(b*NHEAD + h)) * SEQ + qv) * SEQ;

    __shared__ float red[256];

    float vals[8];
    float lmax = -1e30f;
    #pragma unroll
    for (int j = 0; j < 8; j++) {
        int k = tid + j * 256;
        float v = row[k]
                + rel_bias[bucket[k - qv + (SEQ-1)] * NHEAD + h]
                + (1.0f - mask[b*SEQ + k]) * -10000.0f;
        vals[j] = v;
        lmax = fmaxf(lmax, v);
    }
    red[tid] = lmax; __syncthreads();
    for (int st = 128; st > 0; st >>= 1) {
        if (tid < st) red[tid] = fmaxf(red[tid], red[tid + st]);
        __syncthreads();
    }
    float m = red[0];
    __syncthreads();

    float lsum = 0.f;
    #pragma unroll
    for (int j = 0; j < 8; j++) {
        float e = expf(vals[j] - m);
        vals[j] = e;
        lsum += e;
    }
    red[tid] = lsum; __syncthreads();
    for (int st = 128; st > 0; st >>= 1) {
        if (tid < st) red[tid] += red[tid + st];
        __syncthreads();
    }
    float inv = 1.0f / red[0];

    #pragma unroll
    for (int j = 0; j < 8; j++)
        row[tid + j * 256] = vals[j] * inv;
}

// ---------------- gelu_new(a) * g, in place into a ----------------
__global__ void gelumul_kernel(float* __restrict__ a, const float* __restrict__ g,
                               long long n)
{
    long long i = (long long)blockIdx.x * blockDim.x + threadIdx.x;
    if (i >= n) return;
    float x = a[i];
    float t = tanhf(0.7978845608028654f * (x + 0.044715f * x * x * x));
    a[i] = 0.5f * x * (1.0f + t) * g[i];
}

// ---------------- split-bf16 tensor-core GEMM: C = A@B (+Res) ----------------
// BM=128, BK=16, BN templated (128 or 64). 256 threads = 8 warps (4m x 2n).
// Warp tile: 32 x (BN/2), fragments m16n8k16.
// Smem holds uint2{hi_pair, lo_pair} of packed bf16x2 (k-pairs), split ONCE at
// the store stage. Inner loop: pure LDS.64 + MMA.
// acc += ahi*bhi + alo*bhi + ahi*blo   (ll term ~2^-18, dropped).
// A plane: [m][kp], stride 12 uint2  -> frag banks 12g+t4 phase-distinct.
// B plane: [kp][n], stride BN+4      -> (BN+4)%16==4 -> 4*t4+g phase-distinct.
// TRANSB: B element (k,n) = B[n*ldb + k] (register-staged transpose store).
template<int BN, bool TRANSB>
__global__ void __launch_bounds__(256, 2)
mma_gemm(const float* __restrict__ A, const float* __restrict__ B,
         const float* __restrict__ Res, float* __restrict__ C,
         int lda, int ldb, int ldc, int ldr, int K,
         int ZI,
         long long sAo, long long sAi, long long sBo, long long sBi,
         long long sCo, long long sCi)
{
    constexpr int BM = 128, BK = 16;
    constexpr int ASTR = 12;              // uint2 per m-row (8 kp + 4 pad)
    constexpr int BSTR = BN + 4;          // 132 / 68 uint2 per kp-row
    constexpr int WN = BN / 2;            // 64 / 32 cols per warp
    constexpr int NT = WN / 8;            // 8 / 4 n-tiles per warp
    constexpr int NBLK = NT / 4;          // 2 / 1 register-blocked groups
    constexpr int AS_BUF = BM * ASTR;     // 1536
    constexpr int BS_BUF = (BK/2) * BSTR;

    __shared__ __align__(16) uint2 As[2][AS_BUF];
    __shared__ __align__(16) uint2 Bs[2][BS_BUF];

    int z = blockIdx.z;
    int zo = z / ZI, zi = z - zo * ZI;
    A += zo * sAo + zi * sAi;
    B += zo * sBo + zi * sBi;
    C += zo * sCo + zi * sCi;

    int tid = threadIdx.x;
    int lane = tid & 31, wid = tid >> 5;
    int warp_m = wid >> 1, warp_n = wid & 1;
    int g = lane >> 2, t4 = lane & 3;
    int row0 = blockIdx.y * BM;
    int col0 = blockIdx.x * BN;

    float acc[2][NT][4];
    #pragma unroll
    for (int mi = 0; mi < 2; mi++)
        #pragma unroll
        for (int ni = 0; ni < NT; ni++)
            #pragma unroll
            for (int r = 0; r < 4; r++) acc[mi][ni][r] = 0.f;

    // ---- staging coords ----
    // A: 128 x 16 floats, 2 float4 per thread
    int arow[2];
    int acol = (tid & 3) * 4;             // 0,4,8,12 -> kpA = acol/2 (even)
    #pragma unroll
    for (int it = 0; it < 2; it++) arow[it] = (tid + it * 256) >> 2;
    int kpA = acol >> 1;

    // B (!TRANSB): pair-rows. BN=128: all 256 threads; BN=64: first 128.
    int bkp = (BN == 128) ? (tid >> 5) : (tid >> 4);          // 0..7
    int bn4 = (BN == 128) ? ((tid & 31) * 4) : ((tid & 15) * 4);
    bool bact = (BN == 128) || (tid < 128);

    // B (TRANSB): 2 float4 per thread, 4 consecutive k at one n
    int btn[2];
    int btkq = (tid & 3) * 4;
    #pragma unroll
    for (int it = 0; it < 2; it++) btn[it] = (tid + it * 256) >> 2;

    float4 aR[2], bR0, bR1, bRT[2];

    auto ldgA = [&](int k0) {
        #pragma unroll
        for (int it = 0; it < 2; it++)
            aR[it] = *reinterpret_cast<const float4*>(
                A + (long long)(row0 + arow[it]) * lda + k0 + acol);
    };
    auto stsA = [&](int buf) {
        #pragma unroll
        for (int it = 0; it < 2; it++) {
            uint2 p0 = split_pack(aR[it].x, aR[it].y);
            uint2 p1 = split_pack(aR[it].z, aR[it].w);
            *reinterpret_cast<uint4*>(&As[buf][arow[it] * ASTR + kpA]) =
                make_uint4(p0.x, p0.y, p1.x, p1.y);
        }
    };
    auto ldgB = [&](int k0) {              // !TRANSB
        if (bact) {
            const float* b0 = B + (long long)(k0 + 2*bkp) * ldb + col0 + bn4;
            bR0 = *reinterpret_cast<const float4*>(b0);
            bR1 = *reinterpret_cast<const float4*>(b0 + ldb);
        }
    };
    auto stsB = [&](int buf) {             // !TRANSB
        if (bact) {
            uint2 p0 = split_pack(bR0.x, bR1.x);
            uint2 p1 = split_pack(bR0.y, bR1.y);
            uint2 p2 = split_pack(bR0.z, bR1.z);
            uint2 p3 = split_pack(bR0.w, bR1.w);
            uint4* dst = reinterpret_cast<uint4*>(&Bs[buf][bkp * BSTR + bn4]);
            dst[0] = make_uint4(p0.x, p0.y, p1.x, p1.y);
            dst[1] = make_uint4(p2.x, p2.y, p3.x, p3.y);
        }
    };
    auto ldgBT = [&](int k0) {             // TRANSB
        #pragma unroll
        for (int it = 0; it < 2; it++)
            bRT[it] = *reinterpret_cast<const float4*>(
                B + (long long)(col0 + btn[it]) * ldb + k0 + btkq);
    };
    auto stsBT = [&](int buf) {            // TRANSB
        #pragma unroll
        for (int it = 0; it < 2; it++) {
            int kp = btkq >> 1;
            Bs[buf][ kp      * BSTR + btn[it]] = split_pack(bRT[it].x, bRT[it].y);
            Bs[buf][(kp + 1) * BSTR + btn[it]] = split_pack(bRT[it].z, bRT[it].w);
        }
    };

    // prologue
    ldgA(0);
    if (TRANSB) ldgBT(0); else ldgB(0);
    stsA(0);
    if (TRANSB) stsBT(0); else stsB(0);
    __syncthreads();

    int cur = 0;
    for (int k0 = 0; k0 < K; k0 += BK) {
        bool more = (k0 + BK) < K;
        if (more) {
            ldgA(k0 + BK);
            if (TRANSB) ldgBT(k0 + BK); else ldgB(k0 + BK);
        }

        // ---- compute: single m16n8k16 step over BK=16 ----
        uint2 af[2][4];
        #pragma unroll
        for (int mi = 0; mi < 2; mi++) {
            int m = warp_m * 32 + mi * 16 + g;
            const uint2* base = &As[cur][m * ASTR + t4];
            af[mi][0] = base[0];
            af[mi][1] = base[8 * ASTR];
            af[mi][2] = base[4];
            af[mi][3] = base[8 * ASTR + 4];
        }
        #pragma unroll
        for (int nb = 0; nb < NBLK; nb++) {
            uint2 bf[4][2];
            #pragma unroll
            for (int nj = 0; nj < 4; nj++) {
                int n = warp_n * WN + (nb * 4 + nj) * 8 + g;
                bf[nj][0] = Bs[cur][ t4      * BSTR + n];
                bf[nj][1] = Bs[cur][(t4 + 4) * BSTR + n];
            }
            #pragma unroll
            for (int mi = 0; mi < 2; mi++) {
                unsigned AH[4] = {af[mi][0].x, af[mi][1].x, af[mi][2].x, af[mi][3].x};
                unsigned AL[4] = {af[mi][0].y, af[mi][1].y, af[mi][2].y, af[mi][3].y};
                #pragma unroll
                for (int nj = 0; nj < 4; nj++) {
                    unsigned BH[2] = {bf[nj][0].x, bf[nj][1].x};
                    unsigned BL[2] = {bf[nj][0].y, bf[nj][1].y};
                    float* d = acc[mi][nb * 4 + nj];
                    mma_bf16(d, AH, BH);
                    mma_bf16(d, AL, BH);
                    mma_bf16(d, AH, BL);
                }
            }
        }

        if (more) {
            stsA(cur ^ 1);
            if (TRANSB) stsBT(cur ^ 1); else stsB(cur ^ 1);
        }
        __syncthreads();
        cur ^= 1;
    }

    // epilogue: d0,d1 at (r, c..c+1); d2,d3 at (r+8, c..c+1)
    #pragma unroll
    for (int mi = 0; mi < 2; mi++) {
        #pragma unroll
        for (int ni = 0; ni < NT; ni++) {
            int r = row0 + warp_m * 32 + mi * 16 + g;
            int c = col0 + warp_n * WN + ni * 8 + t4 * 2;
            float2 v0 = make_float2(acc[mi][ni][0], acc[mi][ni][1]);
            float2 v1 = make_float2(acc[mi][ni][2], acc[mi][ni][3]);
            if (Res) {
                float2 r0 = *reinterpret_cast<const float2*>(Res + (long long)r * ldr + c);
                float2 r1 = *reinterpret_cast<const float2*>(Res + (long long)(r + 8) * ldr + c);
                v0.x += r0.x; v0.y += r0.y;
                v1.x += r1.x; v1.y += r1.y;
            }
            *reinterpret_cast<float2*>(C + (long long)r * ldc + c) = v0;
            *reinterpret_cast<float2*>(C + (long long)(r + 8) * ldc + c) = v1;
        }
    }
}

// ---------------- host orchestration ----------------
extern "C" void kernel_launch(void* const* d_in, const int* in_sizes, int n_in,
                              void* d_out, int out_size)
{
    const float* hidden   = (const float*)d_in[0];
    const float* mask     = (const float*)d_in[1];
    const float* ln1_w    = (const float*)d_in[2];
    const float* wq       = (const float*)d_in[3];
    const float* wk       = (const float*)d_in[4];
    const float* wv       = (const float*)d_in[5];
    const float* rel_bias = (const float*)d_in[6];
    const float* wo       = (const float*)d_in[7];
    const float* ln2_w    = (const float*)d_in[8];
    const float* w1       = (const float*)d_in[9];
    const float* w2       = (const float*)d_in[10];
    const float* w_out    = (const float*)d_in[11];
    float* out = (float*)d_out;

    void* p;
    cudaGetSymbolAddress(&p, g_normed); float* normed = (float*)p;
    cudaGetSymbolAddress(&p, g_q);      float* q      = (float*)p;
    cudaGetSymbolAddress(&p, g_k);      float* k      = (float*)p;
    cudaGetSymbolAddress(&p, g_v);      float* v      = (float*)p;
    cudaGetSymbolAddress(&p, g_scores); float* scores = (float*)p;
    cudaGetSymbolAddress(&p, g_ctx);    float* ctx    = (float*)p;
    cudaGetSymbolAddress(&p, g_hidden); float* hid    = (float*)p;
    cudaGetSymbolAddress(&p, g_ff1);    float* ff1    = (float*)p;
    cudaGetSymbolAddress(&p, g_ff2);    float* ff2    = (float*)p;
    cudaGetSymbolAddress(&p, g_bucket); int*   bucket = (int*)p;

    const long long SD  = (long long)SEQ * DMODEL;   // per-batch token-plane stride
    const long long SS2 = (long long)SEQ * SEQ;      // per-head score plane

    // 1. RMSNorm #1
    rmsnorm_kernel<<<NTOK, 256>>>(hidden, ln1_w, normed);

    // 2. QKV projections: [4096,1024] x [1024,1024]
    dim3 gProj(DMODEL / 128, NTOK / 128, 1);
    mma_gemm<128,false><<<gProj, 256>>>(normed, wq, nullptr, q,
        DMODEL, DMODEL, DMODEL, 0, DMODEL,
        1, 0,0, 0,0, 0,0);
    mma_gemm<128,false><<<gProj, 256>>>(normed, wk, nullptr, k,
        DMODEL, DMODEL, DMODEL, 0, DMODEL,
        1, 0,0, 0,0, 0,0);
    mma_gemm<128,false><<<gProj, 256>>>(normed, wv, nullptr, v,
        DMODEL, DMODEL, DMODEL, 0, DMODEL,
        1, 0,0, 0,0, 0,0);

    // 3. bucket table
    bucket_kernel<<<(2*SEQ - 1 + 255) / 256, 256>>>(bucket);

    // 4. scores = Q @ K^T per (b,h): M=N=2048, K=64
    dim3 gScore(SEQ / 128, SEQ / 128, NB * NHEAD);
    mma_gemm<128,true><<<gScore, 256>>>(q, k, nullptr, scores,
        DMODEL, DMODEL, SEQ, 0, DHEAD,
        NHEAD, SD, DHEAD, SD, DHEAD, (long long)NHEAD * SS2, SS2);

    // 5. bias + mask + softmax (single pass, in place)
    dim3 gSm(SEQ, NHEAD, NB);
    softmax_kernel<<<gSm, 256>>>(scores, rel_bias, bucket, mask);

    // 6. ctx = probs @ V per (b,h): M=2048, N=64, K=2048
    dim3 gPV(1, SEQ / 128, NB * NHEAD);
    mma_gemm<64,false><<<gPV, 256>>>(scores, v, nullptr, ctx,
        SEQ, DMODEL, DMODEL, 0, SEQ,
        NHEAD, (long long)NHEAD * SS2, SS2, SD, DHEAD, SD, DHEAD);

    // 7. hidden = hidden_in + ctx @ wo
    mma_gemm<128,false><<<gProj, 256>>>(ctx, wo, hidden, hid,
        DMODEL, DMODEL, DMODEL, DMODEL, DMODEL,
        1, 0,0, 0,0, 0,0);

    // 8. RMSNorm #2 (reuse normed buffer)
    rmsnorm_kernel<<<NTOK, 256>>>(hid, ln2_w, normed);

    // 9. ff1 = normed2 @ w1 ; ff2 = normed2 @ w2   [4096,1024]x[1024,4096]
    dim3 gFF(DFF / 128, NTOK / 128, 1);
    mma_gemm<128,false><<<gFF, 256>>>(normed, w1, nullptr, ff1,
        DMODEL, DFF, DFF, 0, DMODEL,
        1, 0,0, 0,0, 0,0);
    mma_gemm<128,false><<<gFF, 256>>>(normed, w2, nullptr, ff2,
        DMODEL, DFF, DFF, 0, DMODEL,
        1, 0,0, 0,0, 0,0);

    // 10. ff1 = gelu_new(ff1) * ff2
    long long nff = (long long)NTOK * DFF;
    gelumul_kernel<<<(unsigned)((nff + 255) / 256), 256>>>(ff1, ff2, nff);

    // 11. out = hidden + ff1 @ w_out   [4096,4096]x[4096,1024]
    mma_gemm<128,false><<<gProj, 256>>>(ff1, w_out, hid, out,
        DFF, DMODEL, DMODEL, DMODEL, DFF,
        1, 0,0, 0,0, 0,0);
}

// round 11
// speedup vs baseline: 2.8283x; 1.1912x over previous
#include <cuda_runtime.h>
#include <cuda_bf16.h>
#include <math.h>

#define NB 2
#define SEQ 2048
#define DMODEL 1024
#define NHEAD 16
#define DHEAD 64
#define DFF 4096
#define NTOK (NB*SEQ)          // 4096

// ---------------- scratch (device globals; no runtime allocation) ----------------
// packed operand format: uint2{ bf16x2(hi_k_even, hi_k_odd), bf16x2(lo_k_even, lo_k_odd) }
__device__ uint2 g_normP[(size_t)NTOK*(DMODEL/2)];
__device__ uint2 g_qP[(size_t)NTOK*(DMODEL/2)];
__device__ uint2 g_kP[(size_t)NTOK*(DMODEL/2)];
__device__ float g_v[(size_t)NTOK*DMODEL];
__device__ uint2 g_vB[(size_t)(NTOK/2)*DMODEL];
__device__ float g_scores[(size_t)NB*NHEAD*SEQ*SEQ];   // 512 MB (fp32, repacked in place)
__device__ uint2 g_ctxP[(size_t)NTOK*(DMODEL/2)];
__device__ float g_hidden[(size_t)NTOK*DMODEL];
__device__ float g_ff1[(size_t)NTOK*DFF];              // repacked in place by gelumul
__device__ float g_ff2[(size_t)NTOK*DFF];
__device__ int   g_bucket[2*SEQ-1];
// packed weights
__device__ uint2 g_wqB[(size_t)(DMODEL/2)*DMODEL];
__device__ uint2 g_wkB[(size_t)(DMODEL/2)*DMODEL];
__device__ uint2 g_wvB[(size_t)(DMODEL/2)*DMODEL];
__device__ uint2 g_woB[(size_t)(DMODEL/2)*DMODEL];
__device__ uint2 g_w1B[(size_t)(DMODEL/2)*DFF];
__device__ uint2 g_w2B[(size_t)(DMODEL/2)*DFF];
__device__ uint2 g_woutB[(size_t)(DFF/2)*DMODEL];

// ---------------- helpers ----------------
__device__ __forceinline__ uint2 split_pack(float e, float o)
{
    __nv_bfloat16 he = __float2bfloat16(e);
    __nv_bfloat16 ho = __float2bfloat16(o);
    __nv_bfloat16 le = __float2bfloat16(e - __bfloat162float(he));
    __nv_bfloat16 lo = __float2bfloat16(o - __bfloat162float(ho));
    unsigned uh = (unsigned)__bfloat16_as_ushort(he) |
                  ((unsigned)__bfloat16_as_ushort(ho) << 16);
    unsigned ul = (unsigned)__bfloat16_as_ushort(le) |
                  ((unsigned)__bfloat16_as_ushort(lo) << 16);
    return make_uint2(uh, ul);
}

__device__ __forceinline__ void mma_bf16(float* d, const unsigned* a, const unsigned* b)
{
    asm volatile(
        "mma.sync.aligned.m16n8k16.row.col.f32.bf16.bf16.f32 "
        "{%0,%1,%2,%3}, {%4,%5,%6,%7}, {%8,%9}, {%0,%1,%2,%3};\n"
        : "+f"(d[0]), "+f"(d[1]), "+f"(d[2]), "+f"(d[3])
        : "r"(a[0]), "r"(a[1]), "r"(a[2]), "r"(a[3]),
          "r"(b[0]), "r"(b[1]));
}

__device__ __forceinline__ void cp16(void* smem_dst, const void* gmem_src)
{
    unsigned s = (unsigned)__cvta_generic_to_shared(smem_dst);
    asm volatile("cp.async.cg.shared.global [%0], [%1], 16;\n"
                 :: "r"(s), "l"(gmem_src));
}
__device__ __forceinline__ void cp_commit()
{
    asm volatile("cp.async.commit_group;\n" ::: "memory");
}
__device__ __forceinline__ void cp_wait_all()
{
    asm volatile("cp.async.wait_group 0;\n" ::: "memory");
}

// ---------------- gmem fp32 -> packed B-format ([kp][n], pairs across k-rows) ----
__global__ void convert_bfmt(const float* __restrict__ src, uint2* __restrict__ dst,
                             int total, int N)
{
    int idx = blockIdx.x * blockDim.x + threadIdx.x;
    if (idx >= total) return;
    int kp = idx / N, n = idx - kp * N;
    dst[idx] = split_pack(src[(size_t)(2*kp) * N + n], src[(size_t)(2*kp+1) * N + n]);
}

// ---------------- RMSNorm -> packed A-format ----------------
__global__ void rmsnorm_kernel(const float* __restrict__ x, const float* __restrict__ w,
                               uint2* __restrict__ out)
{
    int row = blockIdx.x;
    const float2* xr = (const float2*)(x + (long long)row * DMODEL);
    const float2* w2 = (const float2*)w;
    uint2* orow = out + (long long)row * (DMODEL/2);
    int tid = threadIdx.x;

    float s = 0.f;
    for (int i = tid; i < DMODEL/2; i += 256) {
        float2 v = xr[i];
        s += v.x * v.x + v.y * v.y;
    }
    __shared__ float red[256];
    red[tid] = s; __syncthreads();
    for (int st = 128; st > 0; st >>= 1) {
        if (tid < st) red[tid] += red[tid + st];
        __syncthreads();
    }
    float scale = rsqrtf(red[0] / (float)DMODEL + 1e-6f);

    for (int i = tid; i < DMODEL/2; i += 256) {
        float2 v = xr[i]; float2 ww = w2[i];
        orow[i] = split_pack(v.x * scale * ww.x, v.y * scale * ww.y);
    }
}

// ---------------- T5 relative-position bucket table ----------------
__global__ void bucket_kernel(int* __restrict__ table)
{
    int i = blockIdx.x * blockDim.x + threadIdx.x;
    if (i >= 2*SEQ - 1) return;
    int rel = i - (SEQ - 1);                // k - q
    int ret = (rel > 0) ? 16 : 0;
    int n = abs(rel);
    int bucket;
    if (n < 8) {
        bucket = n;
    } else {
        int vl = 8 + (int)(logf((float)n / 8.0f) / logf(16.0f) * 8.0f);
        bucket = min(vl, 15);
    }
    table[i] = ret + bucket;
}

// ---------------- bias + mask + softmax; writes packed probs in place ----------
__global__ void softmax_kernel(float* __restrict__ scores,
                               const float* __restrict__ rel_bias,   // [32,16]
                               const int* __restrict__ bucket,
                               const float* __restrict__ mask)       // [NB,SEQ]
{
    int qv = blockIdx.x, h = blockIdx.y, b = blockIdx.z;
    int tid = threadIdx.x;
    float* row = scores + (((long long)(b*NHEAD + h)) * SEQ + qv) * SEQ;
    const float2* row2 = (const float2*)row;
    uint2* rowP = (uint2*)row;

    __shared__ float red[256];

    float2 vals[4];
    float lmax = -1e30f;
    #pragma unroll
    for (int j = 0; j < 4; j++) {
        int kp = tid + j * 256;
        int k0 = 2*kp, k1 = 2*kp + 1;
        float2 v = row2[kp];
        v.x += rel_bias[bucket[k0 - qv + (SEQ-1)] * NHEAD + h]
             + (1.0f - mask[b*SEQ + k0]) * -10000.0f;
        v.y += rel_bias[bucket[k1 - qv + (SEQ-1)] * NHEAD + h]
             + (1.0f - mask[b*SEQ + k1]) * -10000.0f;
        vals[j] = v;
        lmax = fmaxf(lmax, fmaxf(v.x, v.y));
    }
    red[tid] = lmax; __syncthreads();
    for (int st = 128; st > 0; st >>= 1) {
        if (tid < st) red[tid] = fmaxf(red[tid], red[tid + st]);
        __syncthreads();
    }
    float m = red[0];
    __syncthreads();

    float lsum = 0.f;
    #pragma unroll
    for (int j = 0; j < 4; j++) {
        vals[j].x = expf(vals[j].x - m);
        vals[j].y = expf(vals[j].y - m);
        lsum += vals[j].x + vals[j].y;
    }
    red[tid] = lsum; __syncthreads();
    for (int st = 128; st > 0; st >>= 1) {
        if (tid < st) red[tid] += red[tid + st];
        __syncthreads();
    }
    float inv = 1.0f / red[0];

    #pragma unroll
    for (int j = 0; j < 4; j++) {
        int kp = tid + j * 256;
        rowP[kp] = split_pack(vals[j].x * inv, vals[j].y * inv);
    }
}

// ---------------- gelu_new(a) * g -> packed in place into a ----------------
__global__ void gelumul_kernel(float* __restrict__ a, const float* __restrict__ g,
                               long long npairs)
{
    long long i = (long long)blockIdx.x * blockDim.x + threadIdx.x;
    if (i >= npairs) return;
    float2 x = ((const float2*)a)[i];
    float2 gg = ((const float2*)g)[i];
    float t0 = tanhf(0.7978845608028654f * (x.x + 0.044715f * x.x * x.x * x.x));
    float t1 = tanhf(0.7978845608028654f * (x.y + 0.044715f * x.y * x.y * x.y));
    float r0 = 0.5f * x.x * (1.0f + t0) * gg.x;
    float r1 = 0.5f * x.y * (1.0f + t1) * gg.y;
    ((uint2*)a)[i] = split_pack(r0, r1);
}

// ---------------- split-bf16 tensor-core GEMM on pre-packed operands -----------
// BM=128, BK=16 (8 kp), BN templated (128/64). 256 threads = 8 warps (4m x 2n).
// A: packed A-format [row][kp], lda in uint2. Smem As[m][kp] stride 12, cp.async.
// B !TRANSB: packed B-format [kp][n], ldb in uint2. Smem Bs[kp][n] stride BN+4.
// B TRANSB: packed A-format [n][kp] (e.g. k for Q@K^T). Smem Bs[n][kp] stride 12.
// Inner loop: LDS.64 fragments + 3x mma.bf16 (hh, lh, hl). Zero conversion ALU.
// PACKOUT: epilogue writes packed A-format (n-pairs) instead of fp32.
template<int BN, bool TRANSB, bool PACKOUT>
__global__ void __launch_bounds__(256, 2)
mma_gemm(const uint2* __restrict__ A, const uint2* __restrict__ B,
         const float* __restrict__ Res, void* __restrict__ Cv,
         int lda, int ldb, int ldc, int ldr, int K,
         int ZI,
         long long sAo, long long sAi, long long sBo, long long sBi,
         long long sCo, long long sCi)
{
    constexpr int ASTR = 12;                   // uint2 stride (8 kp + 4 pad)
    constexpr int BSTR = BN + 4;               // !TRANSB: uint2 per kp-row
    constexpr int AS_BUF = 128 * ASTR;         // 1536
    constexpr int BS_BUF = TRANSB ? 128 * ASTR : 8 * BSTR;
    constexpr int WN = BN / 2;                 // 64 / 32 cols per warp
    constexpr int NT = WN / 8;                 // 8 / 4 n-tiles per warp
    constexpr int NBLK = NT / 4;               // 2 / 1

    __shared__ __align__(16) uint2 As[2][AS_BUF];
    __shared__ __align__(16) uint2 Bs[2][BS_BUF];

    int z = blockIdx.z;
    int zo = z / ZI, zi = z - zo * ZI;
    A += zo * sAo + zi * sAi;
    B += zo * sBo + zi * sBi;

    int tid = threadIdx.x;
    int lane = tid & 31, wid = tid >> 5;
    int warp_m = wid >> 1, warp_n = wid & 1;
    int g = lane >> 2, t4 = lane & 3;
    int row0 = blockIdx.y * 128;
    int col0 = blockIdx.x * BN;

    float acc[2][NT][4];
    #pragma unroll
    for (int mi = 0; mi < 2; mi++)
        #pragma unroll
        for (int ni = 0; ni < NT; ni++)
            #pragma unroll
            for (int r = 0; r < 4; r++) acc[mi][ni][r] = 0.f;

    auto issueA = [&](int buf, int kp0) {
        #pragma unroll
        for (int it = 0; it < 2; it++) {
            int idx = tid + it * 256;
            int r = idx >> 2, kq = (idx & 3) * 2;
            cp16(&As[buf][r * ASTR + kq],
                 A + (long long)(row0 + r) * lda + kp0 + kq);
        }
    };
    auto issueB = [&](int buf, int kp0) {
        if (TRANSB) {
            #pragma unroll
            for (int it = 0; it < 2; it++) {
                int idx = tid + it * 256;
                int n = idx >> 2, kq = (idx & 3) * 2;
                cp16(&Bs[buf][n * ASTR + kq],
                     B + (long long)(col0 + n) * ldb + kp0 + kq);
            }
        } else if (BN == 128) {
            #pragma unroll
            for (int it = 0; it < 2; it++) {
                int idx = tid + it * 256;
                int kp = idx >> 6, n = (idx & 63) * 2;
                cp16(&Bs[buf][kp * BSTR + n],
                     B + (long long)(kp0 + kp) * ldb + col0 + n);
            }
        } else {
            int kp = tid >> 5, n = (tid & 31) * 2;
            cp16(&Bs[buf][kp * BSTR + n],
                 B + (long long)(kp0 + kp) * ldb + col0 + n);
        }
    };

    issueA(0, 0); issueB(0, 0); cp_commit();
    cp_wait_all();
    __syncthreads();

    int cur = 0;
    int KP = K >> 1;
    for (int kp0 = 0; kp0 < KP; kp0 += 8) {
        bool more = (kp0 + 8) < KP;
        if (more) {
            issueA(cur ^ 1, kp0 + 8);
            issueB(cur ^ 1, kp0 + 8);
            cp_commit();
        }

        uint2 af[2][4];
        #pragma unroll
        for (int mi = 0; mi < 2; mi++) {
            int m = warp_m * 32 + mi * 16 + g;
            const uint2* base = &As[cur][m * ASTR + t4];
            af[mi][0] = base[0];
            af[mi][1] = base[8 * ASTR];
            af[mi][2] = base[4];
            af[mi][3] = base[8 * ASTR + 4];
        }
        #pragma unroll
        for (int nb = 0; nb < NBLK; nb++) {
            uint2 bf[4][2];
            #pragma unroll
            for (int nj = 0; nj < 4; nj++) {
                int n = warp_n * WN + (nb * 4 + nj) * 8 + g;
                if (TRANSB) {
                    bf[nj][0] = Bs[cur][n * ASTR + t4];
                    bf[nj][1] = Bs[cur][n * ASTR + t4 + 4];
                } else {
                    bf[nj][0] = Bs[cur][ t4      * BSTR + n];
                    bf[nj][1] = Bs[cur][(t4 + 4) * BSTR + n];
                }
            }
            #pragma unroll
            for (int mi = 0; mi < 2; mi++) {
                unsigned AH[4] = {af[mi][0].x, af[mi][1].x, af[mi][2].x, af[mi][3].x};
                unsigned AL[4] = {af[mi][0].y, af[mi][1].y, af[mi][2].y, af[mi][3].y};
                #pragma unroll
                for (int nj = 0; nj < 4; nj++) {
                    unsigned BH[2] = {bf[nj][0].x, bf[nj][1].x};
                    unsigned BL[2] = {bf[nj][0].y, bf[nj][1].y};
                    float* d = acc[mi][nb * 4 + nj];
                    mma_bf16(d, AH, BH);
                    mma_bf16(d, AL, BH);
                    mma_bf16(d, AH, BL);
                }
            }
        }

        if (more) cp_wait_all();
        __syncthreads();
        cur ^= 1;
    }

    // epilogue
    #pragma unroll
    for (int mi = 0; mi < 2; mi++) {
        #pragma unroll
        for (int ni = 0; ni < NT; ni++) {
            int r = row0 + warp_m * 32 + mi * 16 + g;
            int c = col0 + warp_n * WN + ni * 8 + t4 * 2;
            float2 v0 = make_float2(acc[mi][ni][0], acc[mi][ni][1]);
            float2 v1 = make_float2(acc[mi][ni][2], acc[mi][ni][3]);
            if (PACKOUT) {
                uint2* Cp = (uint2*)Cv + zo * sCo + zi * sCi;
                Cp[(long long)r * ldc + (c >> 1)] = split_pack(v0.x, v0.y);
                Cp[(long long)(r + 8) * ldc + (c >> 1)] = split_pack(v1.x, v1.y);
            } else {
                float* C = (float*)Cv + zo * sCo + zi * sCi;
                if (Res) {
                    float2 r0 = *reinterpret_cast<const float2*>(Res + (long long)r * ldr + c);
                    float2 r1 = *reinterpret_cast<const float2*>(Res + (long long)(r + 8) * ldr + c);
                    v0.x += r0.x; v0.y += r0.y;
                    v1.x += r1.x; v1.y += r1.y;
                }
                *reinterpret_cast<float2*>(C + (long long)r * ldc + c) = v0;
                *reinterpret_cast<float2*>(C + (long long)(r + 8) * ldc + c) = v1;
            }
        }
    }
}

// ---------------- host orchestration ----------------
extern "C" void kernel_launch(void* const* d_in, const int* in_sizes, int n_in,
                              void* d_out, int out_size)
{
    const float* hidden   = (const float*)d_in[0];
    const float* mask     = (const float*)d_in[1];
    const float* ln1_w    = (const float*)d_in[2];
    const float* wq       = (const float*)d_in[3];
    const float* wk       = (const float*)d_in[4];
    const float* wv       = (const float*)d_in[5];
    const float* rel_bias = (const float*)d_in[6];
    const float* wo       = (const float*)d_in[7];
    const float* ln2_w    = (const float*)d_in[8];
    const float* w1       = (const float*)d_in[9];
    const float* w2       = (const float*)d_in[10];
    const float* w_out    = (const float*)d_in[11];
    float* out = (float*)d_out;

    void* p;
    cudaGetSymbolAddress(&p, g_normP);  uint2* normP = (uint2*)p;
    cudaGetSymbolAddress(&p, g_qP);     uint2* qP    = (uint2*)p;
    cudaGetSymbolAddress(&p, g_kP);     uint2* kP    = (uint2*)p;
    cudaGetSymbolAddress(&p, g_v);      float* v     = (float*)p;
    cudaGetSymbolAddress(&p, g_vB);     uint2* vB    = (uint2*)p;
    cudaGetSymbolAddress(&p, g_scores); float* scores= (float*)p;
    cudaGetSymbolAddress(&p, g_ctxP);   uint2* ctxP  = (uint2*)p;
    cudaGetSymbolAddress(&p, g_hidden); float* hid   = (float*)p;
    cudaGetSymbolAddress(&p, g_ff1);    float* ff1   = (float*)p;
    cudaGetSymbolAddress(&p, g_ff2);    float* ff2   = (float*)p;
    cudaGetSymbolAddress(&p, g_bucket); int*   bucket= (int*)p;
    cudaGetSymbolAddress(&p, g_wqB);    uint2* wqB   = (uint2*)p;
    cudaGetSymbolAddress(&p, g_wkB);    uint2* wkB   = (uint2*)p;
    cudaGetSymbolAddress(&p, g_wvB);    uint2* wvB   = (uint2*)p;
    cudaGetSymbolAddress(&p, g_woB);    uint2* woB   = (uint2*)p;
    cudaGetSymbolAddress(&p, g_w1B);    uint2* w1B   = (uint2*)p;
    cudaGetSymbolAddress(&p, g_w2B);    uint2* w2B   = (uint2*)p;
    cudaGetSymbolAddress(&p, g_woutB);  uint2* woutB = (uint2*)p;

    // -- weight conversions (per launch; memory-bound, tiny) --
    int nw = (DMODEL/2) * DMODEL;              // 524288
    convert_bfmt<<<(nw + 255)/256, 256>>>(wq, wqB, nw, DMODEL);
    convert_bfmt<<<(nw + 255)/256, 256>>>(wk, wkB, nw, DMODEL);
    convert_bfmt<<<(nw + 255)/256, 256>>>(wv, wvB, nw, DMODEL);
    convert_bfmt<<<(nw + 255)/256, 256>>>(wo, woB, nw, DMODEL);
    int nff_w = (DMODEL/2) * DFF;              // 2M
    convert_bfmt<<<(nff_w + 255)/256, 256>>>(w1, w1B, nff_w, DFF);
    convert_bfmt<<<(nff_w + 255)/256, 256>>>(w2, w2B, nff_w, DFF);
    int nwo = (DFF/2) * DMODEL;                // 2M
    convert_bfmt<<<(nwo + 255)/256, 256>>>(w_out, woutB, nwo, DMODEL);

    const int LDP = DMODEL/2;                  // 512 uint2 per token row
    const long long SDP = (long long)SEQ * LDP;       // packed per-batch token plane
    const long long SS2 = (long long)SEQ * SEQ;       // score plane (fp32)
    const long long SS2P = SS2 / 2;                   // score plane (uint2)

    // 1. RMSNorm #1 -> packed
    rmsnorm_kernel<<<NTOK, 256>>>(hidden, ln1_w, normP);

    // 2. QKV projections: q,k packed out; v fp32 out
    dim3 gProj(DMODEL/128, NTOK/128, 1);
    mma_gemm<128,false,true><<<gProj, 256>>>(normP, wqB, nullptr, qP,
        LDP, DMODEL, LDP, 0, DMODEL, 1, 0,0, 0,0, 0,0);
    mma_gemm<128,false,true><<<gProj, 256>>>(normP, wkB, nullptr, kP,
        LDP, DMODEL, LDP, 0, DMODEL, 1, 0,0, 0,0, 0,0);
    mma_gemm<128,false,false><<<gProj, 256>>>(normP, wvB, nullptr, v,
        LDP, DMODEL, DMODEL, 0, DMODEL, 1, 0,0, 0,0, 0,0);

    // 2b. v -> B-format (pairs across seq rows; batch boundary at even row, safe)
    int nv = (NTOK/2) * DMODEL;                // 2M
    convert_bfmt<<<(nv + 255)/256, 256>>>(v, vB, nv, DMODEL);

    // 3. bucket table
    bucket_kernel<<<(2*SEQ - 1 + 255)/256, 256>>>(bucket);

    // 4. scores = Q @ K^T per (b,h): A=qP, B=kP (both packed A-format), TRANSB
    dim3 gScore(SEQ/128, SEQ/128, NB*NHEAD);
    mma_gemm<128,true,false><<<gScore, 256>>>(qP, kP, nullptr, scores,
        LDP, LDP, SEQ, 0, DHEAD,
        NHEAD, SDP, DHEAD/2, SDP, DHEAD/2, (long long)NHEAD*SS2, SS2);

    // 5. bias + mask + softmax -> packed probs in place
    dim3 gSm(SEQ, NHEAD, NB);
    softmax_kernel<<<gSm, 256>>>(scores, rel_bias, bucket, mask);

    // 6. ctx = probs @ V per (b,h): A=scoresP, B=vB -> ctxP (packed out)
    dim3 gPV(1, SEQ/128, NB*NHEAD);
    mma_gemm<64,false,true><<<gPV, 256>>>((const uint2*)scores, vB, nullptr, ctxP,
        SEQ/2, DMODEL, LDP, 0, SEQ,
        NHEAD, (long long)NHEAD*SS2P, SS2P, (long long)(SEQ/2)*DMODEL, DHEAD,
        SDP, DHEAD/2);

    // 7. hidden = hidden_in + ctx @ wo
    mma_gemm<128,false,false><<<gProj, 256>>>(ctxP, woB, hidden, hid,
        LDP, DMODEL, DMODEL, DMODEL, DMODEL, 1, 0,0, 0,0, 0,0);

    // 8. RMSNorm #2 -> packed
    rmsnorm_kernel<<<NTOK, 256>>>(hid, ln2_w, normP);

    // 9. ff1 = normed2 @ w1 ; ff2 = normed2 @ w2  (fp32 out)
    dim3 gFF(DFF/128, NTOK/128, 1);
    mma_gemm<128,false,false><<<gFF, 256>>>(normP, w1B, nullptr, ff1,
        LDP, DFF, DFF, 0, DMODEL, 1, 0,0, 0,0, 0,0);
    mma_gemm<128,false,false><<<gFF, 256>>>(normP, w2B, nullptr, ff2,
        LDP, DFF, DFF, 0, DMODEL, 1, 0,0, 0,0, 0,0);

    // 10. ff1 = gelu_new(ff1) * ff2 -> packed in place
    long long npairs = (long long)NTOK * DFF / 2;
    gelumul_kernel<<<(unsigned)((npairs + 255)/256), 256>>>(ff1, ff2, npairs);

    // 11. out = hidden + ff1P @ w_out
    mma_gemm<128,false,false><<<gProj, 256>>>((const uint2*)ff1, woutB, hid, out,
        DFF/2, DMODEL, DMODEL, DMODEL, DFF, 1, 0,0, 0,0, 0,0);
}